// round 15
// baseline (speedup 1.0000x reference)
#include <cuda_runtime.h>

// y[b, i] = input[b, i] * diag(weight)[i] + bias[i]
// B = 8192, N = 4096, fp32.
//
// Converged final form: intersection of the three 47.104us winners.
// Kernel 1: gather diag(weight) -> __device__ scratch (tiny).
// Kernel 2: float4 streamer, MLP=2, exact-fit grid (16384 CTAs x 256 thr,
//   2 float4 per thread, zero predication/tail). 256 MB mandatory traffic
//   at the chip's warm mixed L2/DRAM ceiling (~6.9 TB/s effective).

#define N_COLS 4096
#define N4 (N_COLS / 4)          // 1024 float4 columns
#define THREADS 256
#define UNROLL 2

__device__ float g_diag[N_COLS];

__global__ void extract_diag_kernel(const float* __restrict__ weight, int n) {
    int i = blockIdx.x * blockDim.x + threadIdx.x;
    if (i < n) {
        g_diag[i] = weight[(size_t)i * (size_t)(n + 1)];
    }
}

__global__ void __launch_bounds__(THREADS)
scale_bias_kernel(const float4* __restrict__ in,
                  const float4* __restrict__ bias4,
                  float4* __restrict__ out) {
    const float4* __restrict__ d4 = reinterpret_cast<const float4*>(g_diag);

    int idx0   = blockIdx.x * THREADS + threadIdx.x;
    int stride = gridDim.x * THREADS;        // grid covers total4/2 exactly

    // Two front-batched independent loads (MLP = 2), no predication.
    float4 x0 = in[idx0];
    float4 x1 = in[idx0 + stride];

    int c0 = idx0 & (N4 - 1);
    int c1 = (idx0 + stride) & (N4 - 1);

    float4 d0 = d4[c0];                      // 16 KB table, L1-resident
    float4 b0 = bias4[c0];
    float4 d1 = d4[c1];
    float4 b1 = bias4[c1];

    float4 y0, y1;
    y0.x = fmaf(x0.x, d0.x, b0.x);
    y0.y = fmaf(x0.y, d0.y, b0.y);
    y0.z = fmaf(x0.z, d0.z, b0.z);
    y0.w = fmaf(x0.w, d0.w, b0.w);
    y1.x = fmaf(x1.x, d1.x, b1.x);
    y1.y = fmaf(x1.y, d1.y, b1.y);
    y1.z = fmaf(x1.z, d1.z, b1.z);
    y1.w = fmaf(x1.w, d1.w, b1.w);

    out[idx0]          = y0;
    out[idx0 + stride] = y1;
}

extern "C" void kernel_launch(void* const* d_in, const int* in_sizes, int n_in,
                              void* d_out, int out_size) {
    const float* input  = (const float*)d_in[0];   // [B, N]
    const float* weight = (const float*)d_in[1];   // [N, N]
    const float* bias   = (const float*)d_in[2];   // [N]
    float* out = (float*)d_out;

    // 1) gather diagonal
    extract_diag_kernel<<<(N_COLS + 255) / 256, 256>>>(weight, N_COLS);

    // 2) exact-fit streamer: total4 = B*N/4 = 2^23 -> 16384 blocks.
    int total4 = out_size / 4;
    int blocks = total4 / (THREADS * UNROLL);      // 16384
    scale_bias_kernel<<<blocks, THREADS>>>(
        reinterpret_cast<const float4*>(input),
        reinterpret_cast<const float4*>(bias),
        reinterpret_cast<float4*>(out));
}